// round 12
// baseline (speedup 1.0000x reference)
#include <cuda_runtime.h>
#include <cuda_fp16.h>
#include <cstdint>

#define TOKENS    16384
#define DDIM      2048
#define NEXP      64
#define MTILE     128
#define NBLK      (TOKENS / MTILE)       // 128
#define KC        32
#define NCHUNK    (DDIM / KC)            // 64
#define XROWB     160                    // x fp32 row stride (bytes)
#define XBYTES    (MTILE * XROWB)        // 20480
#define WROWB     80                     // W fp16 plane row stride (bytes)
#define WPBYTES   (NEXP * WROWB)         // 5120 per plane
#define STAGE     (XBYTES + 2 * WPBYTES) // 30720
#define SMEM_BYTES (2 * STAGE)           // 61440
#define EPIPITCH  68                     // floats; epilogue smem pitch
#define IDX_COUNT (TOKENS * 2)
#define LO_SCALE  2048.0f
#define LO_INV    (1.0f / 2048.0f)

__device__ __half g_Whi[NEXP * DDIM];        // fp16 hi plane (256 KB)
__device__ __half g_Wlo[NEXP * DDIM];        // fp16 lo plane (pre-scaled 2^11)
__device__ float  g_partials[NBLK * NEXP];
__device__ unsigned int g_ticket = 0;        // last-block election (self-resetting)

// ---------------- PTX helpers (base sm_103-safe) ----------------
__device__ __forceinline__ uint32_t smem_u32(const void* p) {
    uint32_t a;
    asm("{ .reg .u64 t; cvta.to.shared.u64 t, %1; cvt.u32.u64 %0, t; }" : "=r"(a) : "l"(p));
    return a;
}
__device__ __forceinline__ void cpa16(uint32_t dst, const void* src) {
    asm volatile("cp.async.cg.shared.global [%0], [%1], 16;" :: "r"(dst), "l"(src) : "memory");
}
__device__ __forceinline__ void cpa_commit() {
    asm volatile("cp.async.commit_group;" ::: "memory");
}
__device__ __forceinline__ void cpa_wait1() {
    asm volatile("cp.async.wait_group 1;" ::: "memory");
}
__device__ __forceinline__ void ldsm_x4(uint32_t* r, uint32_t addr) {
    asm volatile("ldmatrix.sync.aligned.m8n8.x4.shared.b16 {%0,%1,%2,%3}, [%4];"
                 : "=r"(r[0]), "=r"(r[1]), "=r"(r[2]), "=r"(r[3]) : "r"(addr));
}
__device__ __forceinline__ void lds64(float2& v, uint32_t addr) {
    asm volatile("ld.shared.v2.f32 {%0,%1}, [%2];" : "=f"(v.x), "=f"(v.y) : "r"(addr));
}
// fp32-accumulate HMMA (hi*hi term)
__device__ __forceinline__ void mma_f16_c32(float* d, const uint32_t* a, const uint32_t* b) {
    asm volatile(
        "mma.sync.aligned.m16n8k16.row.col.f32.f16.f16.f32 "
        "{%0,%1,%2,%3}, {%4,%5,%6,%7}, {%8,%9}, {%0,%1,%2,%3};"
        : "+f"(d[0]), "+f"(d[1]), "+f"(d[2]), "+f"(d[3])
        : "r"(a[0]), "r"(a[1]), "r"(a[2]), "r"(a[3]), "r"(b[0]), "r"(b[1]));
}
// fp16-accumulate HMMA (lo terms; potentially double-rate)
__device__ __forceinline__ void mma_f16_c16(uint32_t* d, const uint32_t* a, const uint32_t* b) {
    asm volatile(
        "mma.sync.aligned.m16n8k16.row.col.f16.f16.f16.f16 "
        "{%0,%1}, {%2,%3,%4,%5}, {%6,%7}, {%0,%1};"
        : "+r"(d[0]), "+r"(d[1])
        : "r"(a[0]), "r"(a[1]), "r"(a[2]), "r"(a[3]), "r"(b[0]), "r"(b[1]));
}
// split float2 -> packed fp16 hi + packed fp16 lo*2048
__device__ __forceinline__ void split_f16(float2 v, uint32_t& hi, uint32_t& lo) {
    __half2 h = __float22half2_rn(v);
    float2  hf = __half22float2(h);
    __half2 l = __float22half2_rn(
        make_float2((v.x - hf.x) * LO_SCALE, (v.y - hf.y) * LO_SCALE));
    hi = *reinterpret_cast<uint32_t*>(&h);
    lo = *reinterpret_cast<uint32_t*>(&l);
}

// ============================================================================
// K0: pre-split W into fp16 hi + scaled-lo planes (vectorized: 4 elem/thread)
// ============================================================================
__global__ __launch_bounds__(256)
void k0_split(const float* __restrict__ W) {
    int i = (blockIdx.x * 256 + threadIdx.x) * 4;   // grid covers 131072 elems
    float4 v = *reinterpret_cast<const float4*>(W + i);
    uint32_t h0, l0, h1, l1;
    split_f16(make_float2(v.x, v.y), h0, l0);
    split_f16(make_float2(v.z, v.w), h1, l1);
    *reinterpret_cast<uint2*>(g_Whi + i) = make_uint2(h0, h1);
    *reinterpret_cast<uint2*>(g_Wlo + i) = make_uint2(l0, l1);
}

// ============================================================================
// K1: fused 3xFP16 hi/lo mma.sync GEMM + epilogue + last-block aux reduction.
// 128 blocks x 256 threads; tile M=128 x N=64 x K=2048 (R10-verified staging).
// accH(f32) += Ah*Bh ; accL(f16) += Ah*Bl' + Al'*Bh ; logit = accH + accL/2048.
// ============================================================================
__global__ __launch_bounds__(256)
void k1_fused(const float* __restrict__ x,
              float* __restrict__ out, int out_size) {
    extern __shared__ char dsm[];
    const int tid  = threadIdx.x;
    const int lane = tid & 31;
    const int w    = tid >> 5;
    const int tok0 = blockIdx.x * MTILE;
    const uint32_t sb = smem_u32(dsm);

    // cp.async staging descriptors (R10 layout)
    const float* xsrc[4]; uint32_t xdst[4];
#pragma unroll
    for (int i = 0; i < 4; i++) {
        int f = tid + 256 * i, row = f >> 3, c4 = f & 7;
        xsrc[i] = x + (size_t)(tok0 + row) * DDIM + c4 * 4;
        xdst[i] = (uint32_t)(row * XROWB + c4 * 16);
    }
    const __half* wsrc[2]; uint32_t wdst[2];
#pragma unroll
    for (int i = 0; i < 2; i++) {
        int f = tid, row = f >> 2, c4 = f & 3;
        const __half* plane = i ? g_Wlo : g_Whi;
        wsrc[i] = plane + (size_t)row * DDIM + c4 * 8;
        wdst[i] = (uint32_t)(XBYTES + i * WPBYTES + row * WROWB + c4 * 16);
    }

    const uint32_t abase = (uint32_t)((w * 16 + (lane >> 2)) * XROWB + (lane & 3) * 8);
    const int brow = lane & 7, bsel = lane >> 3;
    const uint32_t blaneoff =
        (uint32_t)((brow + (bsel >> 1) * 8) * WROWB + (bsel & 1) * 16);

    float    accH[8][4];
    uint32_t accL[8][2];
#pragma unroll
    for (int n = 0; n < 8; n++) {
#pragma unroll
        for (int r = 0; r < 4; r++) accH[n][r] = 0.0f;
        accL[n][0] = 0u; accL[n][1] = 0u;
    }

    // Prologue: stage chunks 0 and 1
#pragma unroll
    for (int st = 0; st < 2; st++) {
        const uint32_t B = sb + st * STAGE;
#pragma unroll
        for (int i = 0; i < 4; i++) cpa16(B + xdst[i], xsrc[i] + st * KC);
#pragma unroll
        for (int i = 0; i < 2; i++) cpa16(B + wdst[i], wsrc[i] + st * KC);
        cpa_commit();
    }

    for (int c = 0; c < NCHUNK; c++) {
        cpa_wait1();
        __syncthreads();

        const uint32_t XS = sb + (c & 1) * STAGE;
        const uint32_t WH = XS + XBYTES;
        const uint32_t WL = WH + WPBYTES;

#pragma unroll
        for (int ks = 0; ks < 2; ks++) {
            uint32_t Ah[4], Al[4];
            {
                const uint32_t ab = XS + abase + ks * 64;
                float2 v00, v10, v01, v11;
                lds64(v00, ab);
                lds64(v10, ab + 8 * XROWB);
                lds64(v01, ab + 32);
                lds64(v11, ab + 8 * XROWB + 32);
                split_f16(v00, Ah[0], Al[0]);
                split_f16(v10, Ah[1], Al[1]);
                split_f16(v01, Ah[2], Al[2]);
                split_f16(v11, Ah[3], Al[3]);
            }
            uint32_t Bh[8][2], Bl[8][2];
#pragma unroll
            for (int np = 0; np < 4; np++) {
                uint32_t t[4];
                ldsm_x4(t, WH + (uint32_t)(np * 16 * WROWB + ks * 32) + blaneoff);
                Bh[2 * np][0] = t[0]; Bh[2 * np][1] = t[1];
                Bh[2 * np + 1][0] = t[2]; Bh[2 * np + 1][1] = t[3];
                ldsm_x4(t, WL + (uint32_t)(np * 16 * WROWB + ks * 32) + blaneoff);
                Bl[2 * np][0] = t[0]; Bl[2 * np][1] = t[1];
                Bl[2 * np + 1][0] = t[2]; Bl[2 * np + 1][1] = t[3];
            }
#pragma unroll
            for (int n = 0; n < 8; n++) {
                mma_f16_c32(accH[n], Ah, Bh[n]);
                mma_f16_c16(accL[n], Ah, Bl[n]);
                mma_f16_c16(accL[n], Al, Bh[n]);
            }
        }

        __syncthreads();
        if (c + 2 < NCHUNK) {
            const uint32_t B = sb + (c & 1) * STAGE;
            const int o = (c + 2) * KC;
#pragma unroll
            for (int i = 0; i < 4; i++) cpa16(B + xdst[i], xsrc[i] + o);
#pragma unroll
            for (int i = 0; i < 2; i++) cpa16(B + wdst[i], wsrc[i] + o);
        }
        cpa_commit();
    }
    __syncthreads();

    // ---- fused epilogue ----
    float* lgs = reinterpret_cast<float*>(dsm);
    {
        const int r0 = w * 16 + (lane >> 2);
        const int cb = (lane & 3) * 2;
#pragma unroll
        for (int n = 0; n < 8; n++) {
            const int col = n * 8 + cb;
            float2 lo01 = __half22float2(*reinterpret_cast<__half2*>(&accL[n][0]));
            float2 lo23 = __half22float2(*reinterpret_cast<__half2*>(&accL[n][1]));
            *reinterpret_cast<float2*>(lgs + r0 * EPIPITCH + col) =
                make_float2(accH[n][0] + lo01.x * LO_INV,
                            accH[n][1] + lo01.y * LO_INV);
            *reinterpret_cast<float2*>(lgs + (r0 + 8) * EPIPITCH + col) =
                make_float2(accH[n][2] + lo23.x * LO_INV,
                            accH[n][3] + lo23.y * LO_INV);
        }
    }
    __syncthreads();

    if (tid < MTILE) {
        float* row = lgs + tid * EPIPITCH;
        float lg[64];
#pragma unroll
        for (int e = 0; e < NEXP; e++) lg[e] = row[e];

        float v1 = -1e30f, v2 = -1e30f; int j1 = 0, j2 = 0;
#pragma unroll
        for (int e = 0; e < NEXP; e++) {
            float l = lg[e];
            if (l > v1)      { v2 = v1; j2 = j1; v1 = l; j1 = e; }
            else if (l > v2) { v2 = l;  j2 = e; }
        }
        float s = 0.0f;
#pragma unroll
        for (int e = 0; e < NEXP; e++) { float p = __expf(lg[e] - v1); lg[e] = p; s += p; }
        const float inv = 1.0f / s;

        const int t = tok0 + tid;
        out[t * 2]                 = (float)j1;
        out[t * 2 + 1]             = (float)j2;
        const float w1 = 1.0f / (1.0f + __expf(v2 - v1));
        out[IDX_COUNT + t * 2]     = w1;
        out[IDX_COUNT + t * 2 + 1] = 1.0f - w1;

#pragma unroll
        for (int e = 0; e < NEXP; e++) row[e] = lg[e] * inv;
    }
    __syncthreads();

    if (tid < NEXP) {
        float u = 0.0f;
        for (int r = 0; r < MTILE; r++) u += lgs[r * EPIPITCH + tid];
        g_partials[blockIdx.x * NEXP + tid] = u;
    }

    // ---- last-block aux reduction (replaces k3) ----
    __shared__ unsigned int s_last;
    __syncthreads();
    if (tid == 0) {
        __threadfence();
        s_last = (atomicAdd(&g_ticket, 1u) == NBLK - 1);
    }
    __syncthreads();
    if (s_last) {
        float* red = lgs;                       // reuse epilogue smem
        const int e = tid & 63, part = tid >> 6;  // 4 partitions x 32 blocks
        float s = 0.0f;
#pragma unroll
        for (int i = 0; i < NBLK / 4; i++)
            s += g_partials[(part + 4 * i) * NEXP + e];
        red[tid] = s;
        __syncthreads();
        if (tid < NEXP) {
            float u = red[tid] + red[64 + tid] + red[128 + tid] + red[192 + tid];
            float d = u * (1.0f / (float)TOKENS) - (1.0f / (float)NEXP);
            red[tid] = d * d;
        }
        __syncthreads();
        if (tid == 0) {
            float a = 0.0f;
#pragma unroll
            for (int i = 0; i < NEXP; i++) a += red[i];
            if (out_size > 2 * IDX_COUNT) out[out_size - 1] = a;
            g_ticket = 0;                        // reset for next graph replay
        }
    }
}

// ============================================================================
extern "C" void kernel_launch(void* const* d_in, const int* in_sizes, int n_in,
                              void* d_out, int out_size) {
    const float* x = (const float*)d_in[0];   // [16384, 2048]
    const float* W = (const float*)d_in[1];   // [64, 2048]
    float* out = (float*)d_out;

    cudaFuncSetAttribute(k1_fused, cudaFuncAttributeMaxDynamicSharedMemorySize, SMEM_BYTES);

    k0_split<<<(NEXP * DDIM / 4 + 255) / 256, 256>>>(W);
    k1_fused<<<NBLK, 256, SMEM_BYTES>>>(x, out, out_size);
}

// round 13
// speedup vs baseline: 1.0189x; 1.0189x over previous
#include <cuda_runtime.h>
#include <cuda_fp16.h>
#include <cstdint>

#define TOKENS    16384
#define DDIM      2048
#define NEXP      64
#define MTILE     64
#define NBLK      (TOKENS / MTILE)       // 256
#define KC        32
#define NCHUNK    (DDIM / KC)            // 64
#define XROWB     160                    // x fp32 row stride (bytes)
#define XBYTES    (MTILE * XROWB)        // 10240
#define WROWB     80                     // W fp16 plane row stride (bytes)
#define WPBYTES   (NEXP * WROWB)         // 5120 per plane
#define STAGE     (XBYTES + 2 * WPBYTES) // 20480
#define SMEM_BYTES (2 * STAGE)           // 40960
#define EPIPITCH  68                     // floats; epilogue smem pitch
#define IDX_COUNT (TOKENS * 2)
#define LO_SCALE  2048.0f
#define LO_INV    (1.0f / 2048.0f)

__device__ __half g_Whi[NEXP * DDIM];        // fp16 hi plane (256 KB)
__device__ __half g_Wlo[NEXP * DDIM];        // fp16 lo plane (pre-scaled 2^11)
__device__ float  g_partials[NBLK * NEXP];

// ---------------- PTX helpers (base sm_103-safe) ----------------
__device__ __forceinline__ uint32_t smem_u32(const void* p) {
    uint32_t a;
    asm("{ .reg .u64 t; cvta.to.shared.u64 t, %1; cvt.u32.u64 %0, t; }" : "=r"(a) : "l"(p));
    return a;
}
__device__ __forceinline__ void cpa16(uint32_t dst, const void* src) {
    asm volatile("cp.async.cg.shared.global [%0], [%1], 16;" :: "r"(dst), "l"(src) : "memory");
}
__device__ __forceinline__ void cpa_commit() {
    asm volatile("cp.async.commit_group;" ::: "memory");
}
__device__ __forceinline__ void cpa_wait1() {
    asm volatile("cp.async.wait_group 1;" ::: "memory");
}
__device__ __forceinline__ void ldsm_x4(uint32_t* r, uint32_t addr) {
    asm volatile("ldmatrix.sync.aligned.m8n8.x4.shared.b16 {%0,%1,%2,%3}, [%4];"
                 : "=r"(r[0]), "=r"(r[1]), "=r"(r[2]), "=r"(r[3]) : "r"(addr));
}
__device__ __forceinline__ void lds64(float2& v, uint32_t addr) {
    asm volatile("ld.shared.v2.f32 {%0,%1}, [%2];" : "=f"(v.x), "=f"(v.y) : "r"(addr));
}
__device__ __forceinline__ void mma_f16(float* d, const uint32_t* a, const uint32_t* b) {
    asm volatile(
        "mma.sync.aligned.m16n8k16.row.col.f32.f16.f16.f32 "
        "{%0,%1,%2,%3}, {%4,%5,%6,%7}, {%8,%9}, {%0,%1,%2,%3};"
        : "+f"(d[0]), "+f"(d[1]), "+f"(d[2]), "+f"(d[3])
        : "r"(a[0]), "r"(a[1]), "r"(a[2]), "r"(a[3]), "r"(b[0]), "r"(b[1]));
}
// split float2 -> packed fp16 hi + packed fp16 lo*2048 (tf32-class precision)
__device__ __forceinline__ void split_f16(float2 v, uint32_t& hi, uint32_t& lo) {
    __half2 h = __float22half2_rn(v);
    float2  hf = __half22float2(h);
    __half2 l = __float22half2_rn(
        make_float2((v.x - hf.x) * LO_SCALE, (v.y - hf.y) * LO_SCALE));
    hi = *reinterpret_cast<uint32_t*>(&h);
    lo = *reinterpret_cast<uint32_t*>(&l);
}

// ============================================================================
// K0: pre-split W into fp16 hi + scaled-lo planes (4 elems/thread, vectorized)
// ============================================================================
__global__ __launch_bounds__(256)
void k0_split(const float* __restrict__ W) {
    int i = (blockIdx.x * 256 + threadIdx.x) * 4;   // exact cover: 131072 elems
    float4 v = *reinterpret_cast<const float4*>(W + i);
    uint32_t h0, l0, h1, l1;
    split_f16(make_float2(v.x, v.y), h0, l0);
    split_f16(make_float2(v.z, v.w), h1, l1);
    *reinterpret_cast<uint2*>(g_Whi + i) = make_uint2(h0, h1);
    *reinterpret_cast<uint2*>(g_Wlo + i) = make_uint2(l0, l1);
}

// ============================================================================
// K1: fused 3xFP16 hi/lo mma.sync GEMM + per-token top-2/softmax epilogue.
// 256 blocks x 256 threads, 2 blocks/SM; tile M=64 x N=64 x K=2048.
// Warp w: m16 group g=w&3 (tokens g*16..g*16+15), expert half h=w>>2
// (experts h*32..h*32+31). fp32 accumulators (verified R10 numerics).
// ============================================================================
__global__ __launch_bounds__(256, 2)
void k1_fused(const float* __restrict__ x,
              float* __restrict__ out, int out_size) {
    extern __shared__ char dsm[];
    const int tid  = threadIdx.x;
    const int lane = tid & 31;
    const int w    = tid >> 5;
    const int g    = w & 3;
    const int h    = w >> 2;
    const int tok0 = blockIdx.x * MTILE;
    const uint32_t sb = smem_u32(dsm);

    // x cp.async: 64 rows x 8 float4 = 512 float4; 2 per thread
    const float* xsrc[2]; uint32_t xdst[2];
#pragma unroll
    for (int i = 0; i < 2; i++) {
        int f = tid + 256 * i, row = f >> 3, c4 = f & 7;
        xsrc[i] = x + (size_t)(tok0 + row) * DDIM + c4 * 4;
        xdst[i] = (uint32_t)(row * XROWB + c4 * 16);
    }
    // W cp.async: both planes, 64 rows x 4 x16B each; 2 per thread
    const __half* wsrc[2]; uint32_t wdst[2];
#pragma unroll
    for (int i = 0; i < 2; i++) {
        int row = tid >> 2, c4 = tid & 3;
        const __half* plane = i ? g_Wlo : g_Whi;
        wsrc[i] = plane + (size_t)row * DDIM + c4 * 8;
        wdst[i] = (uint32_t)(XBYTES + i * WPBYTES + row * WROWB + c4 * 16);
    }

    // A LDS.64 base: row = g*16 + lane/4, col pair (lane%4)*2
    const uint32_t abase = (uint32_t)((g * 16 + (lane >> 2)) * XROWB + (lane & 3) * 8);
    // B ldmatrix lane offset within a plane
    const int brow = lane & 7, bsel = lane >> 3;
    const uint32_t blaneoff =
        (uint32_t)((brow + (bsel >> 1) * 8) * WROWB + (bsel & 1) * 16);

    float accH[4][4], accL[4][4];
#pragma unroll
    for (int n = 0; n < 4; n++)
#pragma unroll
        for (int r = 0; r < 4; r++) { accH[n][r] = 0.0f; accL[n][r] = 0.0f; }

    // Prologue: stage chunks 0 and 1
#pragma unroll
    for (int st = 0; st < 2; st++) {
        const uint32_t B = sb + st * STAGE;
#pragma unroll
        for (int i = 0; i < 2; i++) cpa16(B + xdst[i], xsrc[i] + st * KC);
#pragma unroll
        for (int i = 0; i < 2; i++) cpa16(B + wdst[i], wsrc[i] + st * KC);
        cpa_commit();
    }

    for (int c = 0; c < NCHUNK; c++) {
        cpa_wait1();
        __syncthreads();

        const uint32_t XS = sb + (c & 1) * STAGE;
        const uint32_t WH = XS + XBYTES;
        const uint32_t WL = WH + WPBYTES;

#pragma unroll
        for (int ks = 0; ks < 2; ks++) {
            // A fragment (this warp's 16 tokens): fp32 -> fp16 split in regs
            uint32_t Ah[4], Al[4];
            {
                const uint32_t ab = XS + abase + ks * 64;
                float2 v00, v10, v01, v11;
                lds64(v00, ab);
                lds64(v10, ab + 8 * XROWB);
                lds64(v01, ab + 32);
                lds64(v11, ab + 8 * XROWB + 32);
                split_f16(v00, Ah[0], Al[0]);
                split_f16(v10, Ah[1], Al[1]);
                split_f16(v01, Ah[2], Al[2]);
                split_f16(v11, Ah[3], Al[3]);
            }
            // B fragments: this warp's 32 experts (rows h*32..h*32+31)
            uint32_t Bh[4][2], Bl[4][2];
#pragma unroll
            for (int p = 0; p < 2; p++) {
                const int np = 2 * h + p;      // 16-expert panel index
                uint32_t t[4];
                ldsm_x4(t, WH + (uint32_t)(np * 16 * WROWB + ks * 32) + blaneoff);
                Bh[2 * p][0] = t[0]; Bh[2 * p][1] = t[1];
                Bh[2 * p + 1][0] = t[2]; Bh[2 * p + 1][1] = t[3];
                ldsm_x4(t, WL + (uint32_t)(np * 16 * WROWB + ks * 32) + blaneoff);
                Bl[2 * p][0] = t[0]; Bl[2 * p][1] = t[1];
                Bl[2 * p + 1][0] = t[2]; Bl[2 * p + 1][1] = t[3];
            }
#pragma unroll
            for (int n = 0; n < 4; n++) {
                mma_f16(accH[n], Ah, Bh[n]);
                mma_f16(accL[n], Ah, Bl[n]);
                mma_f16(accL[n], Al, Bh[n]);
            }
        }

        __syncthreads();
        if (c + 2 < NCHUNK) {
            const uint32_t B = sb + (c & 1) * STAGE;
            const int o = (c + 2) * KC;
#pragma unroll
            for (int i = 0; i < 2; i++) cpa16(B + xdst[i], xsrc[i] + o);
#pragma unroll
            for (int i = 0; i < 2; i++) cpa16(B + wdst[i], wsrc[i] + o);
        }
        cpa_commit();
    }
    __syncthreads();

    // ---- fused epilogue ----
    // 1) accumulators -> smem logits [64 tokens][EPIPITCH] (~17.4 KB)
    float* lgs = reinterpret_cast<float*>(dsm);
    {
        const int r0 = g * 16 + (lane >> 2);
        const int cb = h * 32 + (lane & 3) * 2;
#pragma unroll
        for (int n = 0; n < 4; n++) {
            const int col = cb + n * 8;
            *reinterpret_cast<float2*>(lgs + r0 * EPIPITCH + col) =
                make_float2(accH[n][0] + accL[n][0] * LO_INV,
                            accH[n][1] + accL[n][1] * LO_INV);
            *reinterpret_cast<float2*>(lgs + (r0 + 8) * EPIPITCH + col) =
                make_float2(accH[n][2] + accL[n][2] * LO_INV,
                            accH[n][3] + accL[n][3] * LO_INV);
        }
    }
    __syncthreads();

    // 2) one thread per TOKEN (tid < 64): top-2 + softmax + outputs + probs
    if (tid < MTILE) {
        float* row = lgs + tid * EPIPITCH;
        float lg[64];
#pragma unroll
        for (int e = 0; e < NEXP; e++) lg[e] = row[e];

        float v1 = -1e30f, v2 = -1e30f; int j1 = 0, j2 = 0;
#pragma unroll
        for (int e = 0; e < NEXP; e++) {
            float l = lg[e];
            if (l > v1)      { v2 = v1; j2 = j1; v1 = l; j1 = e; }
            else if (l > v2) { v2 = l;  j2 = e; }
        }
        float s = 0.0f;
#pragma unroll
        for (int e = 0; e < NEXP; e++) { float p = __expf(lg[e] - v1); lg[e] = p; s += p; }
        const float inv = 1.0f / s;

        const int t = tok0 + tid;
        out[t * 2]                 = (float)j1;
        out[t * 2 + 1]             = (float)j2;
        const float w1 = 1.0f / (1.0f + __expf(v2 - v1));
        out[IDX_COUNT + t * 2]     = w1;
        out[IDX_COUNT + t * 2 + 1] = 1.0f - w1;

#pragma unroll
        for (int e = 0; e < NEXP; e++) row[e] = lg[e] * inv;
    }
    __syncthreads();

    // 3) deterministic per-block usage partials (fixed order over 64 rows)
    if (tid < NEXP) {
        float u = 0.0f;
        for (int r = 0; r < MTILE; r++) u += lgs[r * EPIPITCH + tid];
        g_partials[blockIdx.x * NEXP + tid] = u;
    }
}

// ============================================================================
// K3: aux loss over 256 block partials. 1024 threads, 16-way partition ->
// 16 independent loads/thread; two-level deterministic reduction.
// ============================================================================
__global__ __launch_bounds__(1024)
void k3_aux(float* __restrict__ out, int out_size) {
    __shared__ float red[1024];
    const int tid  = threadIdx.x;
    const int e    = tid & 63;
    const int part = tid >> 6;   // 16 partitions over 256 blocks

    float s = 0.0f;
#pragma unroll
    for (int i = 0; i < NBLK / 16; i++)      // 16 independent loads
        s += g_partials[(part + 16 * i) * NEXP + e];
    red[tid] = s;
    __syncthreads();

    if (tid < NEXP) {
        float u = 0.0f;
#pragma unroll
        for (int p = 0; p < 16; p++) u += red[p * 64 + tid];
        float d = u * (1.0f / (float)TOKENS) - (1.0f / (float)NEXP);
        red[tid] = d * d;
    }
    __syncthreads();

    if (tid == 0) {
        float a = 0.0f;
#pragma unroll
        for (int i = 0; i < NEXP; i++) a += red[i];
        if (out_size > 2 * IDX_COUNT) out[out_size - 1] = a;
    }
}

// ============================================================================
extern "C" void kernel_launch(void* const* d_in, const int* in_sizes, int n_in,
                              void* d_out, int out_size) {
    const float* x = (const float*)d_in[0];   // [16384, 2048]
    const float* W = (const float*)d_in[1];   // [64, 2048]
    float* out = (float*)d_out;

    cudaFuncSetAttribute(k1_fused, cudaFuncAttributeMaxDynamicSharedMemorySize, SMEM_BYTES);

    k0_split<<<NEXP * DDIM / 4 / 256, 256>>>(W);
    k1_fused<<<NBLK, 256, SMEM_BYTES>>>(x, out, out_size);
    k3_aux<<<1, 1024>>>(out, out_size);
}